// round 1
// baseline (speedup 1.0000x reference)
#include <cuda_runtime.h>

#define FFT_N 8192
#define LOGN 13
#define NT 512
#define ROWS_MAX 4096

__device__ float g_best[ROWS_MAX];
__device__ float g_kl[ROWS_MAX];

// Block reduction for exactly NT=512 threads (16 warps). Deterministic tree.
__device__ __forceinline__ float blockReduceSum(float v, float* scratch) {
#pragma unroll
    for (int o = 16; o; o >>= 1) v += __shfl_xor_sync(0xffffffffu, v, o);
    const int warp = threadIdx.x >> 5, lane = threadIdx.x & 31;
    if (lane == 0) scratch[warp] = v;
    __syncthreads();
    if (warp == 0) {
        v = (lane < (NT / 32)) ? scratch[lane] : 0.0f;
#pragma unroll
        for (int o = 8; o; o >>= 1) v += __shfl_xor_sync(0xffffffffu, v, o);
        if (lane == 0) scratch[0] = v;
    }
    __syncthreads();
    float r = scratch[0];
    __syncthreads();  // scratch reusable after this
    return r;
}

__global__ void __launch_bounds__(NT)
row_kernel(const float* __restrict__ preds, const float* __restrict__ targets) {
    // dynamic smem: z[8192] (float2) then tw[4096] (float2) => 96 KiB
    extern __shared__ float2 sm[];
    float2* z  = sm;
    float2* tw = sm + FFT_N;
    __shared__ float scratch[32];
    __shared__ float wcov[(NT / 32) * 31];

    const int row = blockIdx.x;
    const int tid = threadIdx.x;
    const float* __restrict__ pr = preds   + (size_t)row * FFT_N;
    const float* __restrict__ tr = targets + (size_t)row * FFT_N;

    // ---- load rows into smem as complex (pc in .x, tc in .y); accumulate sums
    float sp = 0.0f, st = 0.0f;
#pragma unroll
    for (int i = tid; i < FFT_N; i += NT) {
        float a = pr[i], b = tr[i];
        z[i] = make_float2(a, b);
        sp += a; st += b;
    }
    // twiddle table tw[k] = exp(-2*pi*i*k/N), k in [0, N/2)
#pragma unroll
    for (int k = tid; k < FFT_N / 2; k += NT) {
        float s, c;
        sincosf((-6.283185307179586f / FFT_N) * (float)k, &s, &c);
        tw[k] = make_float2(c, s);
    }
    __syncthreads();
    sp = blockReduceSum(sp, scratch);
    st = blockReduceSum(st, scratch);
    const float mp = sp * (1.0f / FFT_N);
    const float mt = st * (1.0f / FFT_N);

    // ---- center in place, accumulate sum of squares
    float sqp = 0.0f, sqt = 0.0f;
#pragma unroll
    for (int i = tid; i < FFT_N; i += NT) {
        float2 v = z[i];
        v.x -= mp; v.y -= mt;
        z[i] = v;
        sqp = fmaf(v.x, v.x, sqp);
        sqt = fmaf(v.y, v.y, sqt);
    }
    __syncthreads();
    sqp = blockReduceSum(sqp, scratch);
    sqt = blockReduceSum(sqt, scratch);
    // std_p*std_t = sqrt((sqp+eps)*(sqt+eps))
    const float inv_denom = rsqrtf((sqp + 1e-8f) * (sqt + 1e-8f));

    // ---- cross-correlation at 31 shifts: cov[s] = sum_i pc[i]*tc[(i+s-15) mod N]
    float cov[31];
#pragma unroll
    for (int s = 0; s < 31; s++) cov[s] = 0.0f;
    for (int i = tid; i < FFT_N; i += NT) {
        const float p = z[i].x;
        const int base = i - 15;
#pragma unroll
        for (int s = 0; s < 31; s++) {
            cov[s] = fmaf(p, z[(base + s) & (FFT_N - 1)].y, cov[s]);
        }
    }
#pragma unroll
    for (int s = 0; s < 31; s++) {
        float v = cov[s];
#pragma unroll
        for (int o = 16; o; o >>= 1) v += __shfl_xor_sync(0xffffffffu, v, o);
        if ((tid & 31) == 0) wcov[(tid >> 5) * 31 + s] = v;
    }
    __syncthreads();  // all cross-corr reads of z complete; wcov visible
    if (tid < 31) {
        float v = 0.0f;
#pragma unroll
        for (int w = 0; w < NT / 32; w++) v += wcov[w * 31 + tid];
        scratch[tid] = v * inv_denom;  // pearson at this shift
    }
    __syncthreads();
    if (tid == 0) {
        float best = -1.0f;
#pragma unroll
        for (int s = 0; s < 31; s++) best = fmaxf(best, scratch[s]);
        g_best[row] = best;
    }
    __syncthreads();

    // ---- radix-2 DIF FFT in smem (natural in, bit-reversed out)
#pragma unroll
    for (int s = 0; s < LOGN; s++) {
        const int half = FFT_N >> (s + 1);
#pragma unroll
        for (int t = tid; t < FFT_N / 2; t += NT) {
            const int j   = t & (half - 1);
            const int blk = t >> (LOGN - 1 - s);
            const int i0  = (blk << (LOGN - s)) + j;
            const int i1  = i0 + half;
            float2 u = z[i0], v = z[i1];
            float2 w = tw[j << s];
            float dx = u.x - v.x, dy = u.y - v.y;
            z[i0] = make_float2(u.x + v.x, u.y + v.y);
            z[i1] = make_float2(fmaf(dx, w.x, -dy * w.y), fmaf(dx, w.y, dy * w.x));
        }
        __syncthreads();
    }

    // ---- untangle packed real FFTs; sum powers over bins k=1..N/2
    float Sp = 0.0f, St = 0.0f;
#pragma unroll
    for (int k0 = tid; k0 < FFT_N / 2; k0 += NT) {
        const int k = k0 + 1;
        const float2 a = z[__brev((unsigned)k) >> (32 - LOGN)];
        const float2 b = z[__brev((unsigned)(FFT_N - k)) >> (32 - LOGN)];
        float prx = a.x + b.x, pry = a.y - b.y;   // 2*X_k
        float ptx = a.x - b.x, pty = a.y + b.y;   // 2i*Y_k
        Sp += 0.25f * (prx * prx + pry * pry);
        St += 0.25f * (ptx * ptx + pty * pty);
    }
    Sp = blockReduceSum(Sp, scratch);
    St = blockReduceSum(St, scratch);
    const float invSp = 1.0f / (Sp + 1e-8f);
    const float invSt = 1.0f / (St + 1e-8f);

    // ---- KL(prob_t || prob_p); recompute powers (z untouched)
    float kl = 0.0f;
#pragma unroll
    for (int k0 = tid; k0 < FFT_N / 2; k0 += NT) {
        const int k = k0 + 1;
        const float2 a = z[__brev((unsigned)k) >> (32 - LOGN)];
        const float2 b = z[__brev((unsigned)(FFT_N - k)) >> (32 - LOGN)];
        float prx = a.x + b.x, pry = a.y - b.y;
        float ptx = a.x - b.x, pty = a.y + b.y;
        float Pp = 0.25f * (prx * prx + pry * pry);
        float Pt = 0.25f * (ptx * ptx + pty * pty);
        float qp = Pp * invSp;
        float qt = Pt * invSt;
        kl += qt * (__logf(qt + 1e-8f) - __logf(qp + 1e-8f));
    }
    kl = blockReduceSum(kl, scratch);
    if (tid == 0) g_kl[row] = kl;
}

__global__ void __launch_bounds__(NT)
finalize_kernel(float* __restrict__ out, int rows) {
    __shared__ float scratch[32];
    float b = 0.0f, k = 0.0f;
    for (int i = threadIdx.x; i < rows; i += NT) {
        b += g_best[i];
        k += g_kl[i];
    }
    b = blockReduceSum(b, scratch);
    k = blockReduceSum(k, scratch);
    if (threadIdx.x == 0) {
        const float inv_rows = 1.0f / (float)rows;
        float time_loss = 1.0f - b * inv_rows;
        float freq_loss = k * inv_rows;
        out[0] = 0.5f * time_loss + 0.5f * freq_loss;
    }
}

extern "C" void kernel_launch(void* const* d_in, const int* in_sizes, int n_in,
                              void* d_out, int out_size) {
    const float* preds   = (const float*)d_in[0];
    const float* targets = (const float*)d_in[1];
    const int rows = in_sizes[0] / FFT_N;  // 2048

    const size_t smem = (FFT_N + FFT_N / 2) * sizeof(float2);  // 96 KiB
    cudaFuncSetAttribute(row_kernel, cudaFuncAttributeMaxDynamicSharedMemorySize, (int)smem);

    row_kernel<<<rows, NT, smem>>>(preds, targets);
    finalize_kernel<<<1, NT>>>((float*)d_out, rows);
}

// round 2
// speedup vs baseline: 1.5128x; 1.5128x over previous
#include <cuda_runtime.h>

#define FFT_N 8192
#define LOGN 13
#define NT 256
#define NWARP (NT / 32)
#define ROWS_MAX 4096

__device__ float g_best[ROWS_MAX];
__device__ float g_kl[ROWS_MAX];

// skewed layouts: z (float2) max ~2-way conflicts in FFT; ts lane-stride 33 (conflict-free windows)
#define ZIDX(i)  ((i) + ((i) >> 3))
#define TSIDX(i) ((i) + ((i) >> 5))

__device__ __forceinline__ float2 cadd(float2 a, float2 b) { return make_float2(a.x + b.x, a.y + b.y); }
__device__ __forceinline__ float2 csub(float2 a, float2 b) { return make_float2(a.x - b.x, a.y - b.y); }
__device__ __forceinline__ float2 cmul(float2 a, float2 b) {
    return make_float2(fmaf(a.x, b.x, -a.y * b.y), fmaf(a.x, b.y, a.y * b.x));
}

// Deterministic block reduction, NT=256 (8 warps).
__device__ __forceinline__ float blockReduceSum(float v, float* scratch) {
#pragma unroll
    for (int o = 16; o; o >>= 1) v += __shfl_xor_sync(0xffffffffu, v, o);
    const int warp = threadIdx.x >> 5, lane = threadIdx.x & 31;
    if (lane == 0) scratch[warp] = v;
    __syncthreads();
    if (warp == 0) {
        v = (lane < NWARP) ? scratch[lane] : 0.0f;
#pragma unroll
        for (int o = NWARP >> 1; o; o >>= 1) v += __shfl_xor_sync(0xffffffffu, v, o);
        if (lane == 0) scratch[0] = v;
    }
    __syncthreads();
    float r = scratch[0];
    __syncthreads();
    return r;
}

__global__ void __launch_bounds__(NT, 2)
row_kernel(const float* __restrict__ preds, const float* __restrict__ targets) {
    // dynamic smem: z[9216] float2 (72KB) then ts[8448] float (33KB)
    extern __shared__ float smraw[];
    float2* z = (float2*)smraw;
    float*  ts = smraw + 2 * (FFT_N + (FFT_N >> 3));
    __shared__ float scratch[32];
    __shared__ float wcov[NWARP * 31];

    const int row = blockIdx.x;
    const int tid = threadIdx.x;
    const float4* __restrict__ pr4 = (const float4*)(preds   + (size_t)row * FFT_N);
    const float4* __restrict__ tr4 = (const float4*)(targets + (size_t)row * FFT_N);

    // ---- pass 1: load RAW data (no centering needed), write z + ts, accumulate raw stats
    float sp = 0.0f, st = 0.0f, sqp = 0.0f, sqt = 0.0f;
#pragma unroll
    for (int k = 0; k < FFT_N / (4 * NT); k++) {
        const int f = tid + NT * k;
        const float4 p = pr4[f];
        const float4 t = tr4[f];
        const int i0 = 4 * f;
        z[ZIDX(i0 + 0)] = make_float2(p.x, t.x);
        z[ZIDX(i0 + 1)] = make_float2(p.y, t.y);
        z[ZIDX(i0 + 2)] = make_float2(p.z, t.z);
        z[ZIDX(i0 + 3)] = make_float2(p.w, t.w);
        ts[TSIDX(i0 + 0)] = t.x;
        ts[TSIDX(i0 + 1)] = t.y;
        ts[TSIDX(i0 + 2)] = t.z;
        ts[TSIDX(i0 + 3)] = t.w;
        sp += p.x + p.y + p.z + p.w;
        st += t.x + t.y + t.z + t.w;
        sqp = fmaf(p.x, p.x, fmaf(p.y, p.y, fmaf(p.z, p.z, fmaf(p.w, p.w, sqp))));
        sqt = fmaf(t.x, t.x, fmaf(t.y, t.y, fmaf(t.z, t.z, fmaf(t.w, t.w, sqt))));
    }
    sp  = blockReduceSum(sp, scratch);
    st  = blockReduceSum(st, scratch);
    sqp = blockReduceSum(sqp, scratch);
    sqt = blockReduceSum(sqt, scratch);
    const float invN = 1.0f / (float)FFT_N;
    const float sqp_c = sqp - sp * sp * invN;   // centered sum of squares
    const float sqt_c = sqt - st * st * invN;
    const float inv_denom = rsqrtf((sqp_c + 1e-8f) * (sqt_c + 1e-8f));
    const float mean_corr = sp * st * invN;     // subtract from raw covariances

    // ---- cross-correlation: register-blocked, raw data; cov[s]=sum_j p[j]*t[j+s-15]
    float cov[31];
#pragma unroll
    for (int s = 0; s < 31; s++) cov[s] = 0.0f;
#pragma unroll
    for (int q = 0; q < 2; q++) {
        const int base = tid * 32 + q * 16;
        float pk[16];
        const float4* pb = pr4 + (base >> 2);
#pragma unroll
        for (int n = 0; n < 4; n++) {
            float4 v = pb[n];
            pk[4 * n + 0] = v.x; pk[4 * n + 1] = v.y;
            pk[4 * n + 2] = v.z; pk[4 * n + 3] = v.w;
        }
        float twin[46];
#pragma unroll
        for (int m = 0; m < 46; m++) {
            const int idx = (base - 15 + m) & (FFT_N - 1);
            twin[m] = ts[TSIDX(idx)];
        }
#pragma unroll
        for (int k = 0; k < 16; k++)
#pragma unroll
            for (int s = 0; s < 31; s++)
                cov[s] = fmaf(pk[k], twin[k + s], cov[s]);
    }
#pragma unroll
    for (int s = 0; s < 31; s++) {
        float v = cov[s];
#pragma unroll
        for (int o = 16; o; o >>= 1) v += __shfl_xor_sync(0xffffffffu, v, o);
        if ((tid & 31) == 0) wcov[(tid >> 5) * 31 + s] = v;
    }
    __syncthreads();
    if (tid < 31) {
        float v = 0.0f;
#pragma unroll
        for (int w = 0; w < NWARP; w++) v += wcov[w * 31 + tid];
        scratch[tid] = (v - mean_corr) * inv_denom;
    }
    __syncthreads();
    if (tid == 0) {
        float best = -1.0f;
#pragma unroll
        for (int s = 0; s < 31; s++) best = fmaxf(best, scratch[s]);
        g_best[row] = best;
    }
    __syncthreads();

    // ---- fused radix-4 DIF FFT on raw z (bins k>=1 identical to centered FFT)
#pragma unroll
    for (int s = 0; s < 12; s += 2) {
        const int q = FFT_N >> (s + 2);
#pragma unroll
        for (int t = tid; t < FFT_N / 4; t += NT) {
            const int j  = t & (q - 1);
            const int i0 = ((t >> (11 - s)) << (13 - s)) + j;
            float2 A = z[ZIDX(i0)];
            float2 B = z[ZIDX(i0 + q)];
            float2 C = z[ZIDX(i0 + 2 * q)];
            float2 D = z[ZIDX(i0 + 3 * q)];
            float ang = (float)(j << s) * (-6.283185307179586f / (float)FFT_N);
            float s1, c1;
            __sincosf(ang, &s1, &c1);
            const float2 w1 = make_float2(c1, s1);
            const float2 w2 = make_float2(fmaf(c1, c1, -s1 * s1), 2.0f * c1 * s1);
            const float2 w3 = cmul(w1, w2);
            const float2 t0 = cadd(A, C), t1 = csub(A, C);
            const float2 t2 = cadd(B, D), t3 = csub(B, D);
            const float2 e0 = cadd(t0, t2);
            const float2 e1 = csub(t0, t2);
            const float2 f1 = make_float2(t1.x + t3.y, t1.y - t3.x);  // t1 - i*t3
            const float2 f2 = make_float2(t1.x - t3.y, t1.y + t3.x);  // t1 + i*t3
            z[ZIDX(i0)]         = e0;
            z[ZIDX(i0 + q)]     = cmul(e1, w2);
            z[ZIDX(i0 + 2 * q)] = cmul(f1, w1);
            z[ZIDX(i0 + 3 * q)] = cmul(f2, w3);
        }
        __syncthreads();
    }
    // final radix-2 stage (twiddle = 1)
#pragma unroll
    for (int t = tid; t < FFT_N / 2; t += NT) {
        const int i0 = 2 * t;
        float2 u = z[ZIDX(i0)], v = z[ZIDX(i0 + 1)];
        z[ZIDX(i0)]     = cadd(u, v);
        z[ZIDX(i0 + 1)] = csub(u, v);
    }
    __syncthreads();

    // ---- untangle packed real FFTs (bit-reversed order); power sums over bins 1..N/2
    float Sp = 0.0f, St = 0.0f;
#pragma unroll
    for (int r = 0; r < (FFT_N / 2) / NT; r++) {
        const int k = 1 + tid + NT * r;
        const float2 a = z[ZIDX(__brev((unsigned)k) >> (32 - LOGN))];
        const float2 b = z[ZIDX(__brev((unsigned)(FFT_N - k)) >> (32 - LOGN))];
        const float prx = a.x + b.x, pry = a.y - b.y;   // 2*Re(X), 2*Im(X)
        const float ptx = a.x - b.x, pty = a.y + b.y;   // 2*Re(Y)... (times 2)
        Sp = fmaf(0.25f * prx, prx, fmaf(0.25f * pry, pry, Sp));
        St = fmaf(0.25f * ptx, ptx, fmaf(0.25f * pty, pty, St));
    }
    Sp = blockReduceSum(Sp, scratch);
    St = blockReduceSum(St, scratch);
    const float invSp = 1.0f / (Sp + 1e-8f);
    const float invSt = 1.0f / (St + 1e-8f);

    float kl = 0.0f;
#pragma unroll
    for (int r = 0; r < (FFT_N / 2) / NT; r++) {
        const int k = 1 + tid + NT * r;
        const float2 a = z[ZIDX(__brev((unsigned)k) >> (32 - LOGN))];
        const float2 b = z[ZIDX(__brev((unsigned)(FFT_N - k)) >> (32 - LOGN))];
        const float prx = a.x + b.x, pry = a.y - b.y;
        const float ptx = a.x - b.x, pty = a.y + b.y;
        const float Pp = 0.25f * fmaf(prx, prx, pry * pry);
        const float Pt = 0.25f * fmaf(ptx, ptx, pty * pty);
        const float qp = Pp * invSp;
        const float qt = Pt * invSt;
        kl = fmaf(qt, __logf(qt + 1e-8f) - __logf(qp + 1e-8f), kl);
    }
    kl = blockReduceSum(kl, scratch);
    if (tid == 0) g_kl[row] = kl;
}

__global__ void __launch_bounds__(NT)
finalize_kernel(float* __restrict__ out, int rows) {
    __shared__ float scratch[32];
    float b = 0.0f, k = 0.0f;
    for (int i = threadIdx.x; i < rows; i += NT) {
        b += g_best[i];
        k += g_kl[i];
    }
    b = blockReduceSum(b, scratch);
    k = blockReduceSum(k, scratch);
    if (threadIdx.x == 0) {
        const float inv_rows = 1.0f / (float)rows;
        out[0] = 0.5f * (1.0f - b * inv_rows) + 0.5f * (k * inv_rows);
    }
}

extern "C" void kernel_launch(void* const* d_in, const int* in_sizes, int n_in,
                              void* d_out, int out_size) {
    const float* preds   = (const float*)d_in[0];
    const float* targets = (const float*)d_in[1];
    const int rows = in_sizes[0] / FFT_N;

    const size_t smem = (size_t)(FFT_N + (FFT_N >> 3)) * sizeof(float2)
                      + (size_t)(FFT_N + (FFT_N >> 5)) * sizeof(float);
    cudaFuncSetAttribute(row_kernel, cudaFuncAttributeMaxDynamicSharedMemorySize, (int)smem);

    row_kernel<<<rows, NT, smem>>>(preds, targets);
    finalize_kernel<<<1, NT>>>((float*)d_out, rows);
}

// round 3
// speedup vs baseline: 3.6543x; 2.4156x over previous
#include <cuda_runtime.h>

#define FFT_N 8192
#define NT 256
#define NWARP 8
#define ROWS_MAX 4096

__device__ float g_best[ROWS_MAX];
__device__ float g_kl[ROWS_MAX];

// W32^j = exp(-2*pi*i*j/32), j=0..15
__constant__ float TWRE[16] = {
    1.0f,           0.98078528f,   0.92387953f,   0.83146961f,
    0.70710678f,    0.55557023f,   0.38268343f,   0.19509032f,
    0.0f,          -0.19509032f,  -0.38268343f,  -0.55557023f,
   -0.70710678f,   -0.83146961f,  -0.92387953f,  -0.98078528f };
__constant__ float TWIM[16] = {
   -0.0f,          -0.19509032f,  -0.38268343f,  -0.55557023f,
   -0.70710678f,   -0.83146961f,  -0.92387953f,  -0.98078528f,
   -1.0f,          -0.98078528f,  -0.92387953f,  -0.83146961f,
   -0.70710678f,   -0.55557023f,  -0.38268343f,  -0.19509032f };

// smem skews
#define SIDX(i)  ((i) + ((i) >> 4))
#define TSIDX(i) ((i) + ((i) >> 5))

__device__ __forceinline__ float2 cadd(float2 a, float2 b) { return make_float2(a.x + b.x, a.y + b.y); }
__device__ __forceinline__ float2 csub(float2 a, float2 b) { return make_float2(a.x - b.x, a.y - b.y); }
__device__ __forceinline__ float2 cmul(float2 a, float2 b) {
    return make_float2(fmaf(a.x, b.x, -a.y * b.y), fmaf(a.x, b.y, a.y * b.x));
}

__host__ __device__ constexpr int brevc(int x, int bits) {
    int r = 0;
    for (int i = 0; i < bits; i++) r |= ((x >> i) & 1) << (bits - 1 - i);
    return r;
}

// In-register DIF FFT, size M = 1<<LOGM (M divides 32). Natural in, bit-reversed out.
template <int LOGM>
__device__ __forceinline__ void dif_fft(float2* a) {
    constexpr int M = 1 << LOGM;
#pragma unroll
    for (int s = 0; s < LOGM; s++) {
        const int half = M >> (s + 1);
#pragma unroll
        for (int b = 0; b < (M / 2) / half; b++) {
#pragma unroll
            for (int j = 0; j < half; j++) {
                const int i0 = b * 2 * half + j;
                const int i1 = i0 + half;
                const float2 u = a[i0], v = a[i1];
                a[i0] = cadd(u, v);
                const float2 d = csub(u, v);
                const int tw = (j << s) * (32 / M);
                if (tw == 0) {
                    a[i1] = d;
                } else if (tw == 8) {                      // * (-i)
                    a[i1] = make_float2(d.y, -d.x);
                } else {
                    const float c = TWRE[tw], ss = TWIM[tw];
                    a[i1] = make_float2(fmaf(d.x, c, -d.y * ss), fmaf(d.x, ss, d.y * c));
                }
            }
        }
    }
}

__device__ __forceinline__ float4 blockReduceSum4(float4 v) {
    __shared__ float4 scr[NWARP];
#pragma unroll
    for (int o = 16; o; o >>= 1) {
        v.x += __shfl_xor_sync(0xffffffffu, v.x, o);
        v.y += __shfl_xor_sync(0xffffffffu, v.y, o);
        v.z += __shfl_xor_sync(0xffffffffu, v.z, o);
        v.w += __shfl_xor_sync(0xffffffffu, v.w, o);
    }
    const int w = threadIdx.x >> 5, l = threadIdx.x & 31;
    if (l == 0) scr[w] = v;
    __syncthreads();
    if (w == 0) {
        v = (l < NWARP) ? scr[l] : make_float4(0.f, 0.f, 0.f, 0.f);
#pragma unroll
        for (int o = NWARP >> 1; o; o >>= 1) {
            v.x += __shfl_xor_sync(0xffffffffu, v.x, o);
            v.y += __shfl_xor_sync(0xffffffffu, v.y, o);
            v.z += __shfl_xor_sync(0xffffffffu, v.z, o);
            v.w += __shfl_xor_sync(0xffffffffu, v.w, o);
        }
        if (l == 0) scr[0] = v;
    }
    __syncthreads();
    float4 r = scr[0];
    __syncthreads();
    return r;
}

// slot of X[k] in S (phase-2b output layout)
__device__ __forceinline__ int xslot(int k) {
    return (k & 31) * 256 + ((k >> 5) & 15) * 16 + (k >> 9);
}

__global__ void __launch_bounds__(NT, 2)
row_kernel(const float* __restrict__ preds, const float* __restrict__ targets) {
    extern __shared__ float smraw[];
    float2* S  = (float2*)smraw;            // 8704 float2 (skewed)
    float*  ts = smraw + 2 * 8704;          // 8448 floats (skewed)
    __shared__ float wcov[NWARP * 31];
    __shared__ float sred[32];

    const int row = blockIdx.x;
    const int tid = threadIdx.x;
    const float*  __restrict__ pr  = preds   + (size_t)row * FFT_N;
    const float*  __restrict__ tr  = targets + (size_t)row * FFT_N;
    const float4* __restrict__ pr4 = (const float4*)pr;

    // ===== Phase 1: strided load, stats, 32-pt register FFT, twiddle, store to S
    float2 a[32];
    float sp = 0.f, st = 0.f, sqp = 0.f, sqt = 0.f;
#pragma unroll
    for (int n1 = 0; n1 < 32; n1++) {
        const int idx = (n1 << 8) + tid;
        const float p = pr[idx];
        const float t = tr[idx];
        a[n1] = make_float2(p, t);
        ts[TSIDX(idx)] = t;
        sp += p; st += t;
        sqp = fmaf(p, p, sqp);
        sqt = fmaf(t, t, sqt);
    }
    dif_fft<5>(a);
    {
        float s_, c_;
        __sincosf((-6.283185307179586f / FFT_N) * (float)tid, &s_, &c_);
        const float2 w = make_float2(c_, s_);
        float2 cur = make_float2(1.f, 0.f);
#pragma unroll
        for (int k1 = 0; k1 < 32; k1++) {
            const float2 v = a[brevc(k1, 5)];
            S[SIDX(k1 * 256 + tid)] = (k1 == 0) ? v : cmul(v, cur);
            cur = cmul(cur, w);
        }
    }
    const float4 red = blockReduceSum4(make_float4(sp, st, sqp, sqt));  // barriers cover S/ts stores
    const float invN = 1.0f / (float)FFT_N;
    const float sqp_c = red.z - red.x * red.x * invN;
    const float sqt_c = red.w - red.y * red.y * invN;
    const float inv_denom = rsqrtf((sqp_c + 1e-8f) * (sqt_c + 1e-8f));
    const float mean_corr = red.x * red.y * invN;

    // ===== Cross-correlation (register-blocked; ts from smem, preds re-read via L1/L2)
    float cov[31];
#pragma unroll
    for (int s = 0; s < 31; s++) cov[s] = 0.0f;
#pragma unroll
    for (int q = 0; q < 2; q++) {
        const int base = tid * 32 + q * 16;
        float pk[16];
        const float4* pb = pr4 + (base >> 2);
#pragma unroll
        for (int n = 0; n < 4; n++) {
            float4 v = pb[n];
            pk[4 * n + 0] = v.x; pk[4 * n + 1] = v.y;
            pk[4 * n + 2] = v.z; pk[4 * n + 3] = v.w;
        }
        float twin[46];
#pragma unroll
        for (int m = 0; m < 46; m++) {
            const int idx = (base - 15 + m) & (FFT_N - 1);
            twin[m] = ts[TSIDX(idx)];
        }
#pragma unroll
        for (int k = 0; k < 16; k++)
#pragma unroll
            for (int s = 0; s < 31; s++)
                cov[s] = fmaf(pk[k], twin[k + s], cov[s]);
    }
#pragma unroll
    for (int s = 0; s < 31; s++) {
        float v = cov[s];
#pragma unroll
        for (int o = 16; o; o >>= 1) v += __shfl_xor_sync(0xffffffffu, v, o);
        if ((tid & 31) == 0) wcov[(tid >> 5) * 31 + s] = v;
    }
    __syncthreads();
    if (tid < 31) {
        float v = 0.0f;
#pragma unroll
        for (int w = 0; w < NWARP; w++) v += wcov[w * 31 + tid];
        sred[tid] = (v - mean_corr) * inv_denom;
    }
    __syncthreads();
    if (tid == 0) {
        float best = -1.0f;
#pragma unroll
        for (int s = 0; s < 31; s++) best = fmaxf(best, sred[s]);
        g_best[row] = best;
    }

    // ===== Phase 2a: 16-pt FFT over m1 for each (k1, m2); in-place per-thread
    {
        const int m2 = tid & 15;
        float sm_, cm_;
        __sincosf((-6.283185307179586f / 256.0f) * (float)m2, &sm_, &cm_);
        const float2 wm = make_float2(cm_, sm_);
#pragma unroll
        for (int pair = 0; pair < 2; pair++) {
            const int p  = tid + pair * 256;
            const int k1 = p >> 4;
            float2 b[16];
#pragma unroll
            for (int m1 = 0; m1 < 16; m1++)
                b[m1] = S[SIDX(k1 * 256 + m1 * 16 + m2)];
            dif_fft<4>(b);
            float2 cur = make_float2(1.f, 0.f);
#pragma unroll
            for (int j1 = 0; j1 < 16; j1++) {
                const float2 v = b[brevc(j1, 4)];
                S[SIDX(k1 * 256 + j1 * 16 + m2)] = (j1 == 0) ? v : cmul(v, cur);
                cur = cmul(cur, wm);
            }
        }
    }
    __syncthreads();

    // ===== Phase 2b: 16-pt FFT over m2 for each (k1, j1); in-place per-thread
#pragma unroll
    for (int pair = 0; pair < 2; pair++) {
        const int p  = tid + pair * 256;
        const int k1 = p >> 4;
        const int j1 = p & 15;
        float2 c[16];
#pragma unroll
        for (int m2 = 0; m2 < 16; m2++)
            c[m2] = S[SIDX(k1 * 256 + j1 * 16 + m2)];
        dif_fft<4>(c);
#pragma unroll
        for (int j2 = 0; j2 < 16; j2++)
            S[SIDX(k1 * 256 + j1 * 16 + j2)] = c[brevc(j2, 4)];
    }
    __syncthreads();

    // ===== Untangle packed real FFTs; power sums over bins 1..N/2
    float Sp = 0.0f, St = 0.0f;
#pragma unroll
    for (int cbin = 0; cbin < 16; cbin++) {
        const int k = tid * 16 + cbin + 1;
        const float2 za = S[SIDX(xslot(k))];
        const float2 zb = S[SIDX(xslot(FFT_N - k))];
        const float prx = za.x + zb.x, pry = za.y - zb.y;
        const float ptx = za.x - zb.x, pty = za.y + zb.y;
        Sp = fmaf(0.25f * prx, prx, fmaf(0.25f * pry, pry, Sp));
        St = fmaf(0.25f * ptx, ptx, fmaf(0.25f * pty, pty, St));
    }
    {
        const float4 r2 = blockReduceSum4(make_float4(Sp, St, 0.f, 0.f));
        Sp = r2.x; St = r2.y;
    }
    const float invSp = 1.0f / (Sp + 1e-8f);
    const float invSt = 1.0f / (St + 1e-8f);

    float kl = 0.0f;
#pragma unroll
    for (int cbin = 0; cbin < 16; cbin++) {
        const int k = tid * 16 + cbin + 1;
        const float2 za = S[SIDX(xslot(k))];
        const float2 zb = S[SIDX(xslot(FFT_N - k))];
        const float prx = za.x + zb.x, pry = za.y - zb.y;
        const float ptx = za.x - zb.x, pty = za.y + zb.y;
        const float Pp = 0.25f * fmaf(prx, prx, pry * pry);
        const float Pt = 0.25f * fmaf(ptx, ptx, pty * pty);
        const float qp = Pp * invSp;
        const float qt = Pt * invSt;
        kl = fmaf(qt, __logf(qt + 1e-8f) - __logf(qp + 1e-8f), kl);
    }
    {
        const float4 r3 = blockReduceSum4(make_float4(kl, 0.f, 0.f, 0.f));
        if (tid == 0) g_kl[row] = r3.x;
    }
}

__global__ void __launch_bounds__(NT)
finalize_kernel(float* __restrict__ out, int rows) {
    float b = 0.0f, k = 0.0f;
    for (int i = threadIdx.x; i < rows; i += NT) {
        b += g_best[i];
        k += g_kl[i];
    }
    const float4 r = blockReduceSum4(make_float4(b, k, 0.f, 0.f));
    if (threadIdx.x == 0) {
        const float inv_rows = 1.0f / (float)rows;
        out[0] = 0.5f * (1.0f - r.x * inv_rows) + 0.5f * (r.y * inv_rows);
    }
}

extern "C" void kernel_launch(void* const* d_in, const int* in_sizes, int n_in,
                              void* d_out, int out_size) {
    const float* preds   = (const float*)d_in[0];
    const float* targets = (const float*)d_in[1];
    const int rows = in_sizes[0] / FFT_N;

    const size_t smem = (size_t)8704 * sizeof(float2) + (size_t)8448 * sizeof(float);  // 103424 B
    cudaFuncSetAttribute(row_kernel, cudaFuncAttributeMaxDynamicSharedMemorySize, (int)smem);

    row_kernel<<<rows, NT, smem>>>(preds, targets);
    finalize_kernel<<<1, NT>>>((float*)d_out, rows);
}

// round 4
// speedup vs baseline: 3.7281x; 1.0202x over previous
#include <cuda_runtime.h>

#define FFT_N 8192
#define NT 256
#define NWARP 8
#define ROWS_MAX 4096

__device__ float g_best[ROWS_MAX];
__device__ float g_kl[ROWS_MAX];

// W32^j = exp(-2*pi*i*j/32), j=0..15
__constant__ float TWRE[16] = {
    1.0f,           0.98078528f,   0.92387953f,   0.83146961f,
    0.70710678f,    0.55557023f,   0.38268343f,   0.19509032f,
    0.0f,          -0.19509032f,  -0.38268343f,  -0.55557023f,
   -0.70710678f,   -0.83146961f,  -0.92387953f,  -0.98078528f };
__constant__ float TWIM[16] = {
   -0.0f,          -0.19509032f,  -0.38268343f,  -0.55557023f,
   -0.70710678f,   -0.83146961f,  -0.92387953f,  -0.98078528f,
   -1.0f,          -0.98078528f,  -0.92387953f,  -0.83146961f,
   -0.70710678f,   -0.55557023f,  -0.38268343f,  -0.19509032f };

#define SIDX(i)  ((i) + ((i) >> 4))
#define TSIDX(i) ((i) + ((i) >> 5))

union F2U { float2 f; unsigned long long u; };

// Packed f32x2 complex add/sub (1 instr instead of 2). sm_100+ PTX.
__device__ __forceinline__ float2 cadd(float2 a, float2 b) {
    F2U x, y, r; x.f = a; y.f = b;
    asm("add.rn.f32x2 %0, %1, %2;" : "=l"(r.u) : "l"(x.u), "l"(y.u));
    return r.f;
}
__device__ __forceinline__ float2 csub(float2 a, float2 b) {
    F2U x, y, r; x.f = a; y.f = b;
    asm("sub.rn.f32x2 %0, %1, %2;" : "=l"(r.u) : "l"(x.u), "l"(y.u));
    return r.f;
}
__device__ __forceinline__ float2 cmul(float2 a, float2 b) {
    return make_float2(fmaf(a.x, b.x, -a.y * b.y), fmaf(a.x, b.y, a.y * b.x));
}

__host__ __device__ constexpr int brevc(int x, int bits) {
    int r = 0;
    for (int i = 0; i < bits; i++) r |= ((x >> i) & 1) << (bits - 1 - i);
    return r;
}

// In-register DIF FFT, size M = 1<<LOGM (M divides 32). Natural in, bit-reversed out.
template <int LOGM>
__device__ __forceinline__ void dif_fft(float2* a) {
    constexpr int M = 1 << LOGM;
#pragma unroll
    for (int s = 0; s < LOGM; s++) {
        const int half = M >> (s + 1);
#pragma unroll
        for (int b = 0; b < (M / 2) / half; b++) {
#pragma unroll
            for (int j = 0; j < half; j++) {
                const int i0 = b * 2 * half + j;
                const int i1 = i0 + half;
                const float2 u = a[i0], v = a[i1];
                a[i0] = cadd(u, v);
                const float2 d = csub(u, v);
                const int tw = (j << s) * (32 / M);
                if (tw == 0) {
                    a[i1] = d;
                } else if (tw == 8) {                      // * (-i)
                    a[i1] = make_float2(d.y, -d.x);
                } else {
                    const float c = TWRE[tw], ss = TWIM[tw];
                    a[i1] = make_float2(fmaf(d.x, c, -d.y * ss), fmaf(d.x, ss, d.y * c));
                }
            }
        }
    }
}

__device__ __forceinline__ float4 blockReduceSum4(float4 v) {
    __shared__ float4 scr[NWARP];
#pragma unroll
    for (int o = 16; o; o >>= 1) {
        v.x += __shfl_xor_sync(0xffffffffu, v.x, o);
        v.y += __shfl_xor_sync(0xffffffffu, v.y, o);
        v.z += __shfl_xor_sync(0xffffffffu, v.z, o);
        v.w += __shfl_xor_sync(0xffffffffu, v.w, o);
    }
    const int w = threadIdx.x >> 5, l = threadIdx.x & 31;
    if (l == 0) scr[w] = v;
    __syncthreads();
    if (w == 0) {
        v = (l < NWARP) ? scr[l] : make_float4(0.f, 0.f, 0.f, 0.f);
#pragma unroll
        for (int o = NWARP >> 1; o; o >>= 1) {
            v.x += __shfl_xor_sync(0xffffffffu, v.x, o);
            v.y += __shfl_xor_sync(0xffffffffu, v.y, o);
            v.z += __shfl_xor_sync(0xffffffffu, v.z, o);
            v.w += __shfl_xor_sync(0xffffffffu, v.w, o);
        }
        if (l == 0) scr[0] = v;
    }
    __syncthreads();
    float4 r = scr[0];
    __syncthreads();
    return r;
}

// slot of X[k] in S (phase-2b output layout)
__device__ __forceinline__ int xslot(int k) {
    return (k & 31) * 256 + ((k >> 5) & 15) * 16 + (k >> 9);
}

__global__ void __launch_bounds__(NT, 2)
row_kernel(const float* __restrict__ preds, const float* __restrict__ targets) {
    extern __shared__ float smraw[];
    float2* S  = (float2*)smraw;            // 8704 float2 (skewed)
    float*  ts = smraw + 2 * 8704;          // 8448 floats (skewed)
    __shared__ float wcov[NWARP * 31];
    __shared__ float sred[32];

    const int row = blockIdx.x;
    const int tid = threadIdx.x;
    const float*  __restrict__ pr  = preds   + (size_t)row * FFT_N;
    const float*  __restrict__ tr  = targets + (size_t)row * FFT_N;
    const float4* __restrict__ pr4 = (const float4*)pr;

    // ===== Phase 1: strided load, stats, 32-pt register FFT, twiddle, store to S
    float2 a[32];
    float sp = 0.f, st = 0.f, sqp = 0.f, sqt = 0.f;
#pragma unroll
    for (int n1 = 0; n1 < 32; n1++) {
        const int idx = (n1 << 8) + tid;
        const float p = pr[idx];
        const float t = tr[idx];
        a[n1] = make_float2(p, t);
        ts[TSIDX(idx)] = t;
        sp += p; st += t;
        sqp = fmaf(p, p, sqp);
        sqt = fmaf(t, t, sqt);
    }
    dif_fft<5>(a);
    {
        float s_, c_;
        __sincosf((-6.283185307179586f / FFT_N) * (float)tid, &s_, &c_);
        const float2 w1 = make_float2(c_, s_);
        const float2 w2 = cmul(w1, w1);
        const float2 w3 = cmul(w2, w1);
        const float2 w4 = cmul(w2, w2);
        // 4 interleaved twiddle chains (dep depth 8 instead of 31)
        float2 cur[4];
        cur[1] = w1; cur[2] = w2; cur[3] = w3;
        S[SIDX(tid)] = a[0];                               // k1 = 0
#pragma unroll
        for (int g = 1; g < 4; g++) {
            float2 c = cur[g];
#pragma unroll
            for (int k1 = g; k1 < 32; k1 += 4) {
                S[SIDX(k1 * 256 + tid)] = cmul(a[brevc(k1, 5)], c);
                c = cmul(c, w4);
            }
        }
        {
            float2 c = w4;
#pragma unroll
            for (int k1 = 4; k1 < 32; k1 += 4) {
                S[SIDX(k1 * 256 + tid)] = cmul(a[brevc(k1, 5)], c);
                c = cmul(c, w4);
            }
        }
    }
    const float4 red = blockReduceSum4(make_float4(sp, st, sqp, sqt));  // barriers cover S/ts stores
    const float invN = 1.0f / (float)FFT_N;
    const float sqp_c = red.z - red.x * red.x * invN;
    const float sqt_c = red.w - red.y * red.y * invN;
    const float inv_denom = rsqrtf((sqp_c + 1e-8f) * (sqt_c + 1e-8f));
    const float mean_corr = red.x * red.y * invN;

    // ===== Cross-correlation (register-blocked; ts from smem, preds re-read via L1/L2)
    float cov[31];
#pragma unroll
    for (int s = 0; s < 31; s++) cov[s] = 0.0f;
#pragma unroll
    for (int q = 0; q < 2; q++) {
        const int base = tid * 32 + q * 16;
        float pk[16];
        const float4* pb = pr4 + (base >> 2);
#pragma unroll
        for (int n = 0; n < 4; n++) {
            float4 v = pb[n];
            pk[4 * n + 0] = v.x; pk[4 * n + 1] = v.y;
            pk[4 * n + 2] = v.z; pk[4 * n + 3] = v.w;
        }
        float twin[46];
#pragma unroll
        for (int m = 0; m < 46; m++) {
            const int idx = (base - 15 + m) & (FFT_N - 1);
            twin[m] = ts[TSIDX(idx)];
        }
#pragma unroll
        for (int k = 0; k < 16; k++)
#pragma unroll
            for (int s = 0; s < 31; s++)
                cov[s] = fmaf(pk[k], twin[k + s], cov[s]);
    }
#pragma unroll
    for (int s = 0; s < 31; s++) {
        float v = cov[s];
#pragma unroll
        for (int o = 16; o; o >>= 1) v += __shfl_xor_sync(0xffffffffu, v, o);
        if ((tid & 31) == 0) wcov[(tid >> 5) * 31 + s] = v;
    }
    // (no sync yet — post-phase-2a barrier covers wcov visibility)

    // ===== Phase 2a: 16-pt FFT over m1 for each (k1, m2); in-place per-thread
    {
        const int m2 = tid & 15;
        float sm_, cm_;
        __sincosf((-6.283185307179586f / 256.0f) * (float)m2, &sm_, &cm_);
        const float2 wm1 = make_float2(cm_, sm_);
        const float2 wm2 = cmul(wm1, wm1);
        const float2 wm4 = cmul(wm2, wm2);
#pragma unroll
        for (int pair = 0; pair < 2; pair++) {
            const int p  = tid + pair * 256;
            const int k1 = p >> 4;
            float2 b[16];
#pragma unroll
            for (int m1 = 0; m1 < 16; m1++)
                b[m1] = S[SIDX(k1 * 256 + m1 * 16 + m2)];
            dif_fft<4>(b);
            S[SIDX(k1 * 256 + 0 * 16 + m2)] = b[0];
            // 4 interleaved chains over j1
            float2 cg[4];
            cg[1] = wm1; cg[2] = wm2; cg[3] = cmul(wm2, wm1);
#pragma unroll
            for (int g = 1; g < 4; g++) {
                float2 c = cg[g];
#pragma unroll
                for (int j1 = g; j1 < 16; j1 += 4) {
                    S[SIDX(k1 * 256 + j1 * 16 + m2)] = cmul(b[brevc(j1, 4)], c);
                    c = cmul(c, wm4);
                }
            }
            {
                float2 c = wm4;
#pragma unroll
                for (int j1 = 4; j1 < 16; j1 += 4) {
                    S[SIDX(k1 * 256 + j1 * 16 + m2)] = cmul(b[brevc(j1, 4)], c);
                    c = cmul(c, wm4);
                }
            }
        }
    }
    __syncthreads();   // covers phase-2a S writes AND wcov writes

    // ===== Pearson finalize on warp 0 (concurrent with phase 2b on other warps)
    if (tid < 32) {
        if (tid < 31) {
            float v = 0.0f;
#pragma unroll
            for (int w = 0; w < NWARP; w++) v += wcov[w * 31 + tid];
            sred[tid] = (v - mean_corr) * inv_denom;
        }
        __syncwarp();
        if (tid == 0) {
            float best = -1.0f;
#pragma unroll
            for (int s = 0; s < 31; s++) best = fmaxf(best, sred[s]);
            g_best[row] = best;
        }
    }

    // ===== Phase 2b: 16-pt FFT over m2 for each (k1, j1); in-place per-thread
#pragma unroll
    for (int pair = 0; pair < 2; pair++) {
        const int p  = tid + pair * 256;
        const int k1 = p >> 4;
        const int j1 = p & 15;
        float2 c[16];
#pragma unroll
        for (int m2 = 0; m2 < 16; m2++)
            c[m2] = S[SIDX(k1 * 256 + j1 * 16 + m2)];
        dif_fft<4>(c);
#pragma unroll
        for (int j2 = 0; j2 < 16; j2++)
            S[SIDX(k1 * 256 + j1 * 16 + j2)] = c[brevc(j2, 4)];
    }
    __syncthreads();

    // ===== Parseval: power sums come from the stats pass + the Nyquist bin.
    // Sum_{k=1..N/2} |P_k|^2 = (N*sqp_c + |P_{N/2}|^2)/2;  P_{N/2}=Re(Z_4096), T_{N/2}=Im(Z_4096).
    const float2 znyq = S[SIDX(8)];   // xslot(4096) == 8
    const float Sp = 0.5f * fmaf((float)FFT_N, sqp_c, znyq.x * znyq.x);
    const float St = 0.5f * fmaf((float)FFT_N, sqt_c, znyq.y * znyq.y);
    const float invSp = 1.0f / (Sp + 1e-8f);
    const float invSt = 1.0f / (St + 1e-8f);

    // ===== Single untangle + KL pass over bins 1..N/2
    float kl = 0.0f;
#pragma unroll
    for (int cbin = 0; cbin < 16; cbin++) {
        const int k = tid * 16 + cbin + 1;
        const float2 za = S[SIDX(xslot(k))];
        const float2 zb = S[SIDX(xslot(FFT_N - k))];
        const float2 s1 = cadd(za, zb);   // (prx, pty)
        const float2 s2 = csub(za, zb);   // (ptx, pry)
        const float Pp = 0.25f * fmaf(s1.x, s1.x, s2.y * s2.y);
        const float Pt = 0.25f * fmaf(s2.x, s2.x, s1.y * s1.y);
        const float qp = Pp * invSp;
        const float qt = Pt * invSt;
        kl = fmaf(qt, __logf(qt + 1e-8f) - __logf(qp + 1e-8f), kl);
    }
    const float4 r3 = blockReduceSum4(make_float4(kl, 0.f, 0.f, 0.f));
    if (tid == 0) g_kl[row] = r3.x;
}

__global__ void __launch_bounds__(NT)
finalize_kernel(float* __restrict__ out, int rows) {
    float b = 0.0f, k = 0.0f;
    for (int i = threadIdx.x; i < rows; i += NT) {
        b += g_best[i];
        k += g_kl[i];
    }
    const float4 r = blockReduceSum4(make_float4(b, k, 0.f, 0.f));
    if (threadIdx.x == 0) {
        const float inv_rows = 1.0f / (float)rows;
        out[0] = 0.5f * (1.0f - r.x * inv_rows) + 0.5f * (r.y * inv_rows);
    }
}

extern "C" void kernel_launch(void* const* d_in, const int* in_sizes, int n_in,
                              void* d_out, int out_size) {
    const float* preds   = (const float*)d_in[0];
    const float* targets = (const float*)d_in[1];
    const int rows = in_sizes[0] / FFT_N;

    const size_t smem = (size_t)8704 * sizeof(float2) + (size_t)8448 * sizeof(float);  // 103424 B
    cudaFuncSetAttribute(row_kernel, cudaFuncAttributeMaxDynamicSharedMemorySize, (int)smem);

    row_kernel<<<rows, NT, smem>>>(preds, targets);
    finalize_kernel<<<1, NT>>>((float*)d_out, rows);
}